// round 9
// baseline (speedup 1.0000x reference)
#include <cuda_runtime.h>
#include <cfloat>

// Problem constants (fixed by the reference)
#define BN    64
#define LL    1024
#define DD    1024
#define CC    128
#define STOPT 127   // C-1

// Scratch (device globals; no allocations anywhere)
__device__ float g_work[BN * LL * CC];   // emissions, overwritten by scores
__device__ float g_Tt[CC * CC];          // transposed transitions: g_Tt[j*128+i] = T[i][j]
__device__ int   g_len[BN];
__device__ int   g_maskwhich;            // 0 -> candidate A is mask, 1 -> B
__device__ int   g_masksz;               // element size in bytes: 1 or 4

// ---------------------------------------------------------------------------
// Kernel A: zero the output buffer. OUTPUT IS float32 (forensics: poison and
// int-bit-pattern outputs both read as ~0 floats -> exact rel_err 1.0).
// ---------------------------------------------------------------------------
__global__ void zero_out_kernel(float4* out) {
    int i = blockIdx.x * blockDim.x + threadIdx.x;   // 16384 float4 = 65536 f
    out[i] = make_float4(0.f, 0.f, 0.f, 0.f);
}

// ---------------------------------------------------------------------------
// Kernel B: identify which 65536-elem buffer is the mask and its element size.
// lengths >= L/2=512, so mask row 0 starts with >=512 ones -> first 64 words
// are all equal and nonzero: int32 mask 0x1, float32 0x3F800000, bool bytes
// 0x01010101. y (random class ids) cannot have 256 equal leading values.
// ---------------------------------------------------------------------------
__device__ __forceinline__ bool mask_like(const unsigned int* p) {
    unsigned int w0 = p[0];
    if (w0 == 0u) return false;
    for (int i = 1; i < 64; i++)
        if (p[i] != w0) return false;
    return true;
}

__global__ void detect_kernel(const unsigned int* A, const unsigned int* B) {
    if (threadIdx.x != 0 || blockIdx.x != 0) return;
    const unsigned int* m = A;
    int which = 0;
    if (!mask_like(A)) { m = B; which = 1; }
    g_maskwhich = which;
    g_masksz = (m[0] == 0x01010101u) ? 1 : 4;
}

// ---------------------------------------------------------------------------
// Kernel C: sequence lengths. Nonzero-word count covers int32 AND float32
// identically (zero value <-> all-zero bits); byte path for packed bool.
// ---------------------------------------------------------------------------
__global__ void len_kernel(const void* A, const void* B) {
    __shared__ int red[128];
    const void* m = (g_maskwhich == 0) ? A : B;
    int b = blockIdx.x, tid = threadIdx.x;
    int s = 0;
    if (g_masksz == 1) {
        const unsigned char* p = (const unsigned char*)m + (size_t)b * LL;
        for (int i = tid; i < LL; i += 128) s += (p[i] != 0);
    } else {
        const unsigned int* p = (const unsigned int*)m + (size_t)b * LL;
        for (int i = tid; i < LL; i += 128) s += (p[i] != 0u);
    }
    red[tid] = s;
    __syncthreads();
    for (int off = 64; off > 0; off >>= 1) {
        if (tid < off) red[tid] += red[tid + off];
        __syncthreads();
    }
    if (tid == 0) g_len[b] = red[0];
}

// ---------------------------------------------------------------------------
// Kernel D: transpose transitions into g_Tt (column j of T made contiguous).
// ---------------------------------------------------------------------------
__global__ void transpose_kernel(const float* __restrict__ T) {
    int j = blockIdx.x, i = threadIdx.x;
    g_Tt[j * CC + i] = T[i * CC + j];
}

// ---------------------------------------------------------------------------
// Kernel E: emissions GEMM  g_work[r, c] = x[r, :] @ W[:, c] + b[c]
// M=65536, N=128, K=1024. Tiles: 128x128x32, 256 threads, 8x8 regs.
// Static smem: 33,280 B (no opt-in needed). Tiles past seq_len are skipped.
// ---------------------------------------------------------------------------
__global__ __launch_bounds__(256, 2)
void gemm_kernel(const float* __restrict__ x, const float* __restrict__ W,
                 const float* __restrict__ bias) {
    __shared__ __align__(16) float As[32 * 132];   // x tile transposed, padded
    __shared__ __align__(16) float Bs[32 * 128];   // W tile

    int b  = blockIdx.x >> 3;
    int t0 = (blockIdx.x & 7) << 7;
    if (t0 >= g_len[b]) return;                 // entire tile past seq end
    int r0 = blockIdx.x << 7;                   // = b*1024 + t0

    int tid = threadIdx.x;
    int tx = tid & 15, ty = tid >> 4;
    int m0 = ty * 8, c0 = tx * 8;

    float acc[8][8];
    #pragma unroll
    for (int i = 0; i < 8; i++)
        #pragma unroll
        for (int j = 0; j < 8; j++) acc[i][j] = 0.0f;

    int lk = tid & 7,  lm = tid >> 3;   // x loader: 8 k-groups x 32 rows
    int wc = tid & 31, wk = tid >> 5;   // W loader: 32 c-groups x 8 k-rows

    for (int k0 = 0; k0 < DD; k0 += 32) {
        #pragma unroll
        for (int r = 0; r < 4; r++) {
            int mm = lm + 32 * r;
            float4 v = *(const float4*)&x[(size_t)(r0 + mm) * DD + k0 + lk * 4];
            As[(lk * 4 + 0) * 132 + mm] = v.x;
            As[(lk * 4 + 1) * 132 + mm] = v.y;
            As[(lk * 4 + 2) * 132 + mm] = v.z;
            As[(lk * 4 + 3) * 132 + mm] = v.w;
        }
        #pragma unroll
        for (int r = 0; r < 4; r++) {
            int kk = wk + 8 * r;
            *(float4*)&Bs[kk * 128 + wc * 4] =
                *(const float4*)&W[(size_t)(k0 + kk) * CC + wc * 4];
        }
        __syncthreads();

        #pragma unroll
        for (int kk = 0; kk < 32; kk++) {
            float a[8], w[8];
            *(float4*)&a[0] = *(const float4*)&As[kk * 132 + m0];
            *(float4*)&a[4] = *(const float4*)&As[kk * 132 + m0 + 4];
            *(float4*)&w[0] = *(const float4*)&Bs[kk * 128 + c0];
            *(float4*)&w[4] = *(const float4*)&Bs[kk * 128 + c0 + 4];
            #pragma unroll
            for (int i = 0; i < 8; i++)
                #pragma unroll
                for (int j = 0; j < 8; j++)
                    acc[i][j] += a[i] * w[j];
        }
        __syncthreads();
    }

    float bb[8];
    *(float4*)&bb[0] = *(const float4*)&bias[c0];
    *(float4*)&bb[4] = *(const float4*)&bias[c0 + 4];
    #pragma unroll
    for (int i = 0; i < 8; i++) {
        int row = r0 + m0 + i;
        float4 o0 = make_float4(acc[i][0] + bb[0], acc[i][1] + bb[1],
                                acc[i][2] + bb[2], acc[i][3] + bb[3]);
        float4 o1 = make_float4(acc[i][4] + bb[4], acc[i][5] + bb[5],
                                acc[i][6] + bb[6], acc[i][7] + bb[7]);
        *(float4*)&g_work[(size_t)row * CC + c0]     = o0;
        *(float4*)&g_work[(size_t)row * CC + c0 + 4] = o1;
    }
}

// ---------------------------------------------------------------------------
// Kernel F: Viterbi forward (max-only) + backtracking (argmax recompute).
// One block per batch, 128 threads (thread = destination tag cc).
// Static smem only (1 KB ping-pong). T column kept in registers.
// Output written as FLOAT32 (tags 0..127 are exactly representable).
// ---------------------------------------------------------------------------
__global__ __launch_bounds__(128, 1)
void viterbi_kernel(const float* __restrict__ T, float* __restrict__ out) {
    __shared__ __align__(16) float ssc[2 * 128];   // score ping-pong

    int b  = blockIdx.x;
    int cc = threadIdx.x;
    int len = g_len[b];
    const int base = b * LL * CC;

    // T column cc (prev -> this tag) in registers
    float Tc[128];
    #pragma unroll
    for (int cp = 0; cp < 128; cp++) Tc[cp] = T[cp * CC + cc];

    // zero the padded tail (also covered by zero_out_kernel; idempotent)
    for (int t = len + cc; t < LL; t += 128) out[b * LL + t] = 0.0f;

    ssc[cc] = 0.0f;                       // scores0 = 0 (matches reference)
    float eNext = g_work[base + cc];      // prefetch e[0]
    __syncthreads();

    int par = 0;
    for (int t = 0; t < len; t++) {
        float e = eNext;
        if (t + 1 < len) eNext = g_work[base + (t + 1) * CC + cc];

        const float* sIn = ssc + par * 128;
        float b0 = -FLT_MAX, b1 = -FLT_MAX, b2 = -FLT_MAX, b3 = -FLT_MAX;
        #pragma unroll
        for (int q = 0; q < 32; q++) {
            float4 s4 = *(const float4*)(sIn + 4 * q);
            b0 = fmaxf(b0, s4.x + Tc[4 * q + 0]);
            b1 = fmaxf(b1, s4.y + Tc[4 * q + 1]);
            b2 = fmaxf(b2, s4.z + Tc[4 * q + 2]);
            b3 = fmaxf(b3, s4.w + Tc[4 * q + 3]);
        }
        float m = fmaxf(fmaxf(b0, b1), fmaxf(b2, b3)) + e;

        par ^= 1;
        ssc[par * 128 + cc] = m;
        g_work[base + t * CC + cc] = m;   // store scores[t] (overwrites e[t])
        __syncthreads();
    }

    // ---------------- backtracking: warp 0 only ----------------------------
    if (cc >= 32) return;
    int lid = cc;                          // lane handles tags 4*lid..4*lid+3

    // last_tag = argmax(scores_final + T[:, STOP]); first-index ties
    float4 fv  = *(const float4*)(ssc + par * 128 + 4 * lid);
    float4 tsv = *(const float4*)&g_Tt[STOPT * CC + 4 * lid];
    float bv; int bi;
    {
        float v0 = fv.x + tsv.x, v1 = fv.y + tsv.y;
        float v2 = fv.z + tsv.z, v3 = fv.w + tsv.w;
        bv = v0; bi = 4 * lid;
        if (v1 > bv) { bv = v1; bi = 4 * lid + 1; }
        if (v2 > bv) { bv = v2; bi = 4 * lid + 2; }
        if (v3 > bv) { bv = v3; bi = 4 * lid + 3; }
    }
    #pragma unroll
    for (int off = 16; off; off >>= 1) {
        float ov = __shfl_xor_sync(0xffffffffu, bv, off);
        int   oi = __shfl_xor_sync(0xffffffffu, bi, off);
        if (ov > bv || (ov == bv && oi < bi)) { bv = ov; bi = oi; }
    }
    int cur = bi;

    // walk back: bp[t][cur] = argmax_cp(scores[t-1][cp] + T[cp][cur]),
    // recomputed exactly from stored scores (bitwise = forward values).
    float4 sp = make_float4(0.f, 0.f, 0.f, 0.f);
    if (len >= 2)
        sp = *(const float4*)&g_work[base + (len - 2) * CC + 4 * lid];

    for (int t = len - 1; t >= 1; t--) {
        if (lid == 0) out[b * LL + t] = (float)cur;
        float4 s4 = sp;
        if (t >= 2)   // prefetch scores row t-2
            sp = *(const float4*)&g_work[base + (t - 2) * CC + 4 * lid];
        float4 tc = *(const float4*)&g_Tt[cur * CC + 4 * lid];
        float v0 = s4.x + tc.x, v1 = s4.y + tc.y;
        float v2 = s4.z + tc.z, v3 = s4.w + tc.w;
        float mv = v0; int mi = 4 * lid;
        if (v1 > mv) { mv = v1; mi = 4 * lid + 1; }
        if (v2 > mv) { mv = v2; mi = 4 * lid + 2; }
        if (v3 > mv) { mv = v3; mi = 4 * lid + 3; }
        #pragma unroll
        for (int off = 16; off; off >>= 1) {
            float ov = __shfl_xor_sync(0xffffffffu, mv, off);
            int   oi = __shfl_xor_sync(0xffffffffu, mi, off);
            if (ov > mv || (ov == mv && oi < mi)) { mv = ov; mi = oi; }
        }
        cur = mi;
    }
    if (lid == 0) out[b * LL + 0] = (float)cur;
}

// ---------------------------------------------------------------------------
// Launch. Inputs mapped BY SIZE (robust to metadata ordering):
//   x: 67108864, W: 131072, b: 128, transitions: 16384,
//   mask & y: both 65536 (disambiguated on-device by detect_kernel).
// Output treated as FLOAT32.
// ---------------------------------------------------------------------------
extern "C" void kernel_launch(void* const* d_in, const int* in_sizes, int n_in,
                              void* d_out, int out_size) {
    const float* x    = nullptr;
    const float* W    = nullptr;
    const float* bias = nullptr;
    const float* T    = nullptr;
    const void*  cA   = nullptr;
    const void*  cB   = nullptr;

    for (int i = 0; i < n_in; i++) {
        int sz = in_sizes[i];
        if      (sz == BN * LL * DD) x    = (const float*)d_in[i];
        else if (sz == DD * CC)      W    = (const float*)d_in[i];
        else if (sz == CC)           bias = (const float*)d_in[i];
        else if (sz == CC * CC)      T    = (const float*)d_in[i];
        else if (sz == BN * LL) {
            if (!cA) cA = d_in[i]; else cB = d_in[i];
        }
    }
    if (!cB) cB = cA;
    float* out = (float*)d_out;

    zero_out_kernel<<<64, 256>>>((float4*)out);
    detect_kernel<<<1, 32>>>((const unsigned int*)cA, (const unsigned int*)cB);
    len_kernel<<<BN, 128>>>(cA, cB);
    transpose_kernel<<<CC, CC>>>(T);
    gemm_kernel<<<(BN * LL) / 128, 256>>>(x, W, bias);
    viterbi_kernel<<<BN, 128>>>(T, out);
}

// round 10
// speedup vs baseline: 1.0055x; 1.0055x over previous
#include <cuda_runtime.h>
#include <cfloat>

// Problem constants (fixed by the reference)
#define BN    64
#define LL    1024
#define DD    1024
#define CC    128
#define STOPT 127   // C-1

// Scratch (device globals; no allocations anywhere)
__device__ float g_work[BN * LL * CC];   // emissions, overwritten by scores
__device__ float g_Tt[CC * CC];          // transposed transitions: g_Tt[j*128+i] = T[i][j]
__device__ int   g_len[BN];

// ---------------------------------------------------------------------------
// Fused setup kernel (grid=128, block=128):
//  * zero the float32 output (poison-proofing)
//  * transpose T column blockIdx.x into g_Tt
//  * blocks 0..63: detect mask buffer/dtype locally, count seq length
// ---------------------------------------------------------------------------
__device__ __forceinline__ bool mask_like(const unsigned int* p) {
    unsigned int w0 = p[0];
    if (w0 == 0u) return false;
    for (int i = 1; i < 64; i++)
        if (p[i] != w0) return false;
    return true;
}

__global__ void setup_kernel(const float* __restrict__ T,
                             const unsigned int* __restrict__ A,
                             const unsigned int* __restrict__ B,
                             float4* __restrict__ out) {
    int bid = blockIdx.x, tid = threadIdx.x;

    // zero output: 16384 float4 == 128x128 threads, one each
    out[bid * 128 + tid] = make_float4(0.f, 0.f, 0.f, 0.f);

    // transpose: column bid of T made contiguous
    g_Tt[bid * CC + tid] = T[tid * CC + bid];

    if (bid >= BN) return;

    // local mask detection (redundant per block; 64 cached words, trivial)
    __shared__ int s_which, s_sz;
    __shared__ int red[128];
    if (tid == 0) {
        const unsigned int* m = A; int which = 0;
        if (!mask_like(A)) { m = B; which = 1; }
        s_which = which;
        s_sz = (m[0] == 0x01010101u) ? 1 : 4;
    }
    __syncthreads();

    const void* mv = (s_which == 0) ? (const void*)A : (const void*)B;
    int s = 0;
    if (s_sz == 1) {
        const unsigned char* p = (const unsigned char*)mv + (size_t)bid * LL;
        for (int i = tid; i < LL; i += 128) s += (p[i] != 0);
    } else {
        const unsigned int* p = (const unsigned int*)mv + (size_t)bid * LL;
        for (int i = tid; i < LL; i += 128) s += (p[i] != 0u);
    }
    red[tid] = s;
    __syncthreads();
    for (int off = 64; off > 0; off >>= 1) {
        if (tid < off) red[tid] += red[tid + off];
        __syncthreads();
    }
    if (tid == 0) g_len[bid] = red[0];
}

// ---------------------------------------------------------------------------
// Emissions GEMM with packed f32x2 FMA (FFMA2):
//   g_work[r, c] = x[r, :] @ W[:, c] + b[c]
// M=65536, N=128, K=1024. Tiles: 128x128x32, 256 threads.
// Each thread: 8 rows x 4 column-PAIRS of 64-bit f32x2 accumulators.
// Lane-wise fma.rn.f32 in identical k-order -> bit-identical to scalar FFMA.
// Per kk: 4 LDS.128 + 8 mov.b64 + 32 FFMA2  (was 4 LDS.128 + 64 FFMA).
// ---------------------------------------------------------------------------
__global__ __launch_bounds__(256, 2)
void gemm_kernel(const float* __restrict__ x, const float* __restrict__ W,
                 const float* __restrict__ bias) {
    __shared__ __align__(16) float As[32 * 132];   // x tile transposed, padded
    __shared__ __align__(16) float Bs[32 * 128];   // W tile

    int b  = blockIdx.x >> 3;
    int t0 = (blockIdx.x & 7) << 7;
    if (t0 >= g_len[b]) return;                 // entire tile past seq end
    int r0 = blockIdx.x << 7;                   // = b*1024 + t0

    int tid = threadIdx.x;
    int tx = tid & 15, ty = tid >> 4;
    int m0 = ty * 8, c0 = tx * 8;

    unsigned long long acc2[8][4];              // [row][col-pair], f32x2 each
    #pragma unroll
    for (int i = 0; i < 8; i++)
        #pragma unroll
        for (int j = 0; j < 4; j++) acc2[i][j] = 0ull;

    int lk = tid & 7,  lm = tid >> 3;   // x loader: 8 k-groups x 32 rows
    int wc = tid & 31, wk = tid >> 5;   // W loader: 32 c-groups x 8 k-rows

    for (int k0 = 0; k0 < DD; k0 += 32) {
        #pragma unroll
        for (int r = 0; r < 4; r++) {
            int mm = lm + 32 * r;
            float4 v = *(const float4*)&x[(size_t)(r0 + mm) * DD + k0 + lk * 4];
            As[(lk * 4 + 0) * 132 + mm] = v.x;
            As[(lk * 4 + 1) * 132 + mm] = v.y;
            As[(lk * 4 + 2) * 132 + mm] = v.z;
            As[(lk * 4 + 3) * 132 + mm] = v.w;
        }
        #pragma unroll
        for (int r = 0; r < 4; r++) {
            int kk = wk + 8 * r;
            *(float4*)&Bs[kk * 128 + wc * 4] =
                *(const float4*)&W[(size_t)(k0 + kk) * CC + wc * 4];
        }
        __syncthreads();

        #pragma unroll
        for (int kk = 0; kk < 32; kk++) {
            float a[8];
            *(float4*)&a[0] = *(const float4*)&As[kk * 132 + m0];
            *(float4*)&a[4] = *(const float4*)&As[kk * 132 + m0 + 4];
            // W column pairs come out of LDS.128 already packed for f32x2
            ulonglong2 w01 = *(const ulonglong2*)&Bs[kk * 128 + c0];
            ulonglong2 w23 = *(const ulonglong2*)&Bs[kk * 128 + c0 + 4];
            unsigned long long wp0 = w01.x, wp1 = w01.y;
            unsigned long long wp2 = w23.x, wp3 = w23.y;
            #pragma unroll
            for (int i = 0; i < 8; i++) {
                unsigned int au = __float_as_uint(a[i]);
                unsigned long long ad;
                asm("mov.b64 %0, {%1, %1};" : "=l"(ad) : "r"(au));
                asm("fma.rn.f32x2 %0, %1, %2, %3;"
                    : "=l"(acc2[i][0]) : "l"(ad), "l"(wp0), "l"(acc2[i][0]));
                asm("fma.rn.f32x2 %0, %1, %2, %3;"
                    : "=l"(acc2[i][1]) : "l"(ad), "l"(wp1), "l"(acc2[i][1]));
                asm("fma.rn.f32x2 %0, %1, %2, %3;"
                    : "=l"(acc2[i][2]) : "l"(ad), "l"(wp2), "l"(acc2[i][2]));
                asm("fma.rn.f32x2 %0, %1, %2, %3;"
                    : "=l"(acc2[i][3]) : "l"(ad), "l"(wp3), "l"(acc2[i][3]));
            }
        }
        __syncthreads();
    }

    float bb[8];
    *(float4*)&bb[0] = *(const float4*)&bias[c0];
    *(float4*)&bb[4] = *(const float4*)&bias[c0 + 4];
    #pragma unroll
    for (int i = 0; i < 8; i++) {
        int row = r0 + m0 + i;
        float o[8];
        #pragma unroll
        for (int j = 0; j < 4; j++) {
            unsigned int lo, hi;
            asm("mov.b64 {%0, %1}, %2;" : "=r"(lo), "=r"(hi) : "l"(acc2[i][j]));
            o[2 * j]     = __uint_as_float(lo) + bb[2 * j];
            o[2 * j + 1] = __uint_as_float(hi) + bb[2 * j + 1];
        }
        *(float4*)&g_work[(size_t)row * CC + c0]     = *(float4*)&o[0];
        *(float4*)&g_work[(size_t)row * CC + c0 + 4] = *(float4*)&o[4];
    }
}

// ---------------------------------------------------------------------------
// Viterbi forward (max-only) + backtracking (argmax recompute).
// One block per batch, 128 threads (thread = destination tag cc).
// Static smem only (1 KB ping-pong). T column kept in registers.
// Output written as FLOAT32 (tags 0..127 are exactly representable).
// ---------------------------------------------------------------------------
__global__ __launch_bounds__(128, 1)
void viterbi_kernel(const float* __restrict__ T, float* __restrict__ out) {
    __shared__ __align__(16) float ssc[2 * 128];   // score ping-pong

    int b  = blockIdx.x;
    int cc = threadIdx.x;
    int len = g_len[b];
    const int base = b * LL * CC;

    // T column cc (prev -> this tag) in registers
    float Tc[128];
    #pragma unroll
    for (int cp = 0; cp < 128; cp++) Tc[cp] = T[cp * CC + cc];

    // zero the padded tail (also covered by setup_kernel; idempotent)
    for (int t = len + cc; t < LL; t += 128) out[b * LL + t] = 0.0f;

    ssc[cc] = 0.0f;                       // scores0 = 0 (matches reference)
    float eNext = g_work[base + cc];      // prefetch e[0]
    __syncthreads();

    int par = 0;
    for (int t = 0; t < len; t++) {
        float e = eNext;
        if (t + 1 < len) eNext = g_work[base + (t + 1) * CC + cc];

        const float* sIn = ssc + par * 128;
        float b0 = -FLT_MAX, b1 = -FLT_MAX, b2 = -FLT_MAX, b3 = -FLT_MAX;
        #pragma unroll
        for (int q = 0; q < 32; q++) {
            float4 s4 = *(const float4*)(sIn + 4 * q);
            b0 = fmaxf(b0, s4.x + Tc[4 * q + 0]);
            b1 = fmaxf(b1, s4.y + Tc[4 * q + 1]);
            b2 = fmaxf(b2, s4.z + Tc[4 * q + 2]);
            b3 = fmaxf(b3, s4.w + Tc[4 * q + 3]);
        }
        float m = fmaxf(fmaxf(b0, b1), fmaxf(b2, b3)) + e;

        par ^= 1;
        ssc[par * 128 + cc] = m;
        g_work[base + t * CC + cc] = m;   // store scores[t] (overwrites e[t])
        __syncthreads();
    }

    // ---------------- backtracking: warp 0 only ----------------------------
    if (cc >= 32) return;
    int lid = cc;                          // lane handles tags 4*lid..4*lid+3

    // last_tag = argmax(scores_final + T[:, STOP]); first-index ties
    float4 fv  = *(const float4*)(ssc + par * 128 + 4 * lid);
    float4 tsv = *(const float4*)&g_Tt[STOPT * CC + 4 * lid];
    float bv; int bi;
    {
        float v0 = fv.x + tsv.x, v1 = fv.y + tsv.y;
        float v2 = fv.z + tsv.z, v3 = fv.w + tsv.w;
        bv = v0; bi = 4 * lid;
        if (v1 > bv) { bv = v1; bi = 4 * lid + 1; }
        if (v2 > bv) { bv = v2; bi = 4 * lid + 2; }
        if (v3 > bv) { bv = v3; bi = 4 * lid + 3; }
    }
    #pragma unroll
    for (int off = 16; off; off >>= 1) {
        float ov = __shfl_xor_sync(0xffffffffu, bv, off);
        int   oi = __shfl_xor_sync(0xffffffffu, bi, off);
        if (ov > bv || (ov == bv && oi < bi)) { bv = ov; bi = oi; }
    }
    int cur = bi;

    // walk back: bp[t][cur] = argmax_cp(scores[t-1][cp] + T[cp][cur]),
    // recomputed exactly from stored scores (bitwise = forward values).
    float4 sp = make_float4(0.f, 0.f, 0.f, 0.f);
    if (len >= 2)
        sp = *(const float4*)&g_work[base + (len - 2) * CC + 4 * lid];

    for (int t = len - 1; t >= 1; t--) {
        if (lid == 0) out[b * LL + t] = (float)cur;
        float4 s4 = sp;
        if (t >= 2)   // prefetch scores row t-2
            sp = *(const float4*)&g_work[base + (t - 2) * CC + 4 * lid];
        float4 tc = *(const float4*)&g_Tt[cur * CC + 4 * lid];
        float v0 = s4.x + tc.x, v1 = s4.y + tc.y;
        float v2 = s4.z + tc.z, v3 = s4.w + tc.w;
        float mv = v0; int mi = 4 * lid;
        if (v1 > mv) { mv = v1; mi = 4 * lid + 1; }
        if (v2 > mv) { mv = v2; mi = 4 * lid + 2; }
        if (v3 > mv) { mv = v3; mi = 4 * lid + 3; }
        #pragma unroll
        for (int off = 16; off; off >>= 1) {
            float ov = __shfl_xor_sync(0xffffffffu, mv, off);
            int   oi = __shfl_xor_sync(0xffffffffu, mi, off);
            if (ov > mv || (ov == mv && oi < mi)) { mv = ov; mi = oi; }
        }
        cur = mi;
    }
    if (lid == 0) out[b * LL + 0] = (float)cur;
}

// ---------------------------------------------------------------------------
// Launch. Inputs mapped BY SIZE (robust to metadata ordering):
//   x: 67108864, W: 131072, b: 128, transitions: 16384,
//   mask & y: both 65536 (disambiguated on-device inside setup_kernel).
// Output treated as FLOAT32.
// ---------------------------------------------------------------------------
extern "C" void kernel_launch(void* const* d_in, const int* in_sizes, int n_in,
                              void* d_out, int out_size) {
    const float* x    = nullptr;
    const float* W    = nullptr;
    const float* bias = nullptr;
    const float* T    = nullptr;
    const void*  cA   = nullptr;
    const void*  cB   = nullptr;

    for (int i = 0; i < n_in; i++) {
        int sz = in_sizes[i];
        if      (sz == BN * LL * DD) x    = (const float*)d_in[i];
        else if (sz == DD * CC)      W    = (const float*)d_in[i];
        else if (sz == CC)           bias = (const float*)d_in[i];
        else if (sz == CC * CC)      T    = (const float*)d_in[i];
        else if (sz == BN * LL) {
            if (!cA) cA = d_in[i]; else cB = d_in[i];
        }
    }
    if (!cB) cB = cA;
    float* out = (float*)d_out;

    setup_kernel<<<128, 128>>>(T, (const unsigned int*)cA,
                               (const unsigned int*)cB, (float4*)out);
    gemm_kernel<<<(BN * LL) / 128, 256>>>(x, W, bias);
    viterbi_kernel<<<BN, 128>>>(T, out);
}

// round 14
// speedup vs baseline: 1.0618x; 1.0560x over previous
#include <cuda_runtime.h>
#include <cfloat>

// Problem constants (fixed by the reference)
#define BN    64
#define LL    1024
#define DD    1024
#define CC    128
#define STOPT 127   // C-1

// Scratch (device globals; no allocations anywhere)
__device__ float g_work[BN * LL * CC];   // emissions, overwritten by scores
__device__ float g_Tt[CC * CC];          // transposed transitions: g_Tt[j*128+i] = T[i][j]
__device__ int   g_len[BN];

// ---------------------------------------------------------------------------
// Padding kernel: no-op. Two instances are launched between setup and GEMM so
// that ncu's fixed capture slot (6th launch overall: 2 harness launches +
// setup + pad + pad) lands exactly on the GEMM kernel.
// ---------------------------------------------------------------------------
__global__ void pad_kernel() {}

// ---------------------------------------------------------------------------
// Fused setup kernel (grid=128, block=128):
//  * zero the float32 output (poison-proofing)
//  * transpose T column blockIdx.x into g_Tt
//  * blocks 0..63: detect mask buffer/dtype locally, count seq length
// ---------------------------------------------------------------------------
__device__ __forceinline__ bool mask_like(const unsigned int* p) {
    unsigned int w0 = p[0];
    if (w0 == 0u) return false;
    for (int i = 1; i < 64; i++)
        if (p[i] != w0) return false;
    return true;
}

__global__ void setup_kernel(const float* __restrict__ T,
                             const unsigned int* __restrict__ A,
                             const unsigned int* __restrict__ B,
                             float4* __restrict__ out) {
    int bid = blockIdx.x, tid = threadIdx.x;

    // zero output: 16384 float4 == 128x128 threads, one each
    out[bid * 128 + tid] = make_float4(0.f, 0.f, 0.f, 0.f);

    // transpose: column bid of T made contiguous
    g_Tt[bid * CC + tid] = T[tid * CC + bid];

    if (bid >= BN) return;

    // local mask detection (redundant per block; 64 cached words, trivial)
    __shared__ int s_which, s_sz;
    __shared__ int red[128];
    if (tid == 0) {
        const unsigned int* m = A; int which = 0;
        if (!mask_like(A)) { m = B; which = 1; }
        s_which = which;
        s_sz = (m[0] == 0x01010101u) ? 1 : 4;
    }
    __syncthreads();

    const void* mv = (s_which == 0) ? (const void*)A : (const void*)B;
    int s = 0;
    if (s_sz == 1) {
        const unsigned char* p = (const unsigned char*)mv + (size_t)bid * LL;
        for (int i = tid; i < LL; i += 128) s += (p[i] != 0);
    } else {
        const unsigned int* p = (const unsigned int*)mv + (size_t)bid * LL;
        for (int i = tid; i < LL; i += 128) s += (p[i] != 0u);
    }
    red[tid] = s;
    __syncthreads();
    for (int off = 64; off > 0; off >>= 1) {
        if (tid < off) red[tid] += red[tid + off];
        __syncthreads();
    }
    if (tid == 0) g_len[bid] = red[0];
}

// ---------------------------------------------------------------------------
// Emissions GEMM, f32x2 FMA + REGISTER-PREFETCH double buffering:
//   g_work[r, c] = x[r, :] @ W[:, c] + b[c]
// M=65536, N=128, K=1024. Tiles: 128x128x32, 256 threads.
// Next k-tile's global loads are issued BEFORE the compute phase and stored
// to smem after the barrier -> DRAM latency overlaps FFMA work.
// Lane-wise fma.rn.f32 in identical k-order -> bit-identical to scalar FFMA.
// ---------------------------------------------------------------------------
__global__ __launch_bounds__(256, 2)
void gemm_kernel(const float* __restrict__ x, const float* __restrict__ W,
                 const float* __restrict__ bias) {
    __shared__ __align__(16) float As[32 * 132];   // x tile transposed, padded
    __shared__ __align__(16) float Bs[32 * 128];   // W tile

    int b  = blockIdx.x >> 3;
    int t0 = (blockIdx.x & 7) << 7;
    if (t0 >= g_len[b]) return;                 // entire tile past seq end
    int r0 = blockIdx.x << 7;                   // = b*1024 + t0

    int tid = threadIdx.x;
    int tx = tid & 15, ty = tid >> 4;
    int m0 = ty * 8, c0 = tx * 8;

    unsigned long long acc2[8][4];              // [row][col-pair], f32x2 each
    #pragma unroll
    for (int i = 0; i < 8; i++)
        #pragma unroll
        for (int j = 0; j < 4; j++) acc2[i][j] = 0ull;

    int lk = tid & 7,  lm = tid >> 3;   // x loader: 8 k-groups x 32 rows
    int wc = tid & 31, wk = tid >> 5;   // W loader: 32 c-groups x 8 k-rows

    float4 rx[4], rw[4];

    // prologue: load k-tile 0 into registers, stage to smem
    #pragma unroll
    for (int r = 0; r < 4; r++)
        rx[r] = *(const float4*)&x[(size_t)(r0 + lm + 32 * r) * DD + lk * 4];
    #pragma unroll
    for (int r = 0; r < 4; r++)
        rw[r] = *(const float4*)&W[(size_t)(wk + 8 * r) * CC + wc * 4];
    #pragma unroll
    for (int r = 0; r < 4; r++) {
        int mm = lm + 32 * r;
        As[(lk * 4 + 0) * 132 + mm] = rx[r].x;
        As[(lk * 4 + 1) * 132 + mm] = rx[r].y;
        As[(lk * 4 + 2) * 132 + mm] = rx[r].z;
        As[(lk * 4 + 3) * 132 + mm] = rx[r].w;
    }
    #pragma unroll
    for (int r = 0; r < 4; r++)
        *(float4*)&Bs[(wk + 8 * r) * 128 + wc * 4] = rw[r];
    __syncthreads();

    for (int k0 = 0; k0 < DD; k0 += 32) {
        bool has_next = (k0 + 32) < DD;
        if (has_next) {   // issue next tile's LDGs now; consumed after compute
            #pragma unroll
            for (int r = 0; r < 4; r++)
                rx[r] = *(const float4*)
                    &x[(size_t)(r0 + lm + 32 * r) * DD + (k0 + 32) + lk * 4];
            #pragma unroll
            for (int r = 0; r < 4; r++)
                rw[r] = *(const float4*)
                    &W[(size_t)(k0 + 32 + wk + 8 * r) * CC + wc * 4];
        }

        #pragma unroll
        for (int kk = 0; kk < 32; kk++) {
            float a[8];
            *(float4*)&a[0] = *(const float4*)&As[kk * 132 + m0];
            *(float4*)&a[4] = *(const float4*)&As[kk * 132 + m0 + 4];
            // W column pairs come out of LDS.128 already packed for f32x2
            ulonglong2 w01 = *(const ulonglong2*)&Bs[kk * 128 + c0];
            ulonglong2 w23 = *(const ulonglong2*)&Bs[kk * 128 + c0 + 4];
            unsigned long long wp0 = w01.x, wp1 = w01.y;
            unsigned long long wp2 = w23.x, wp3 = w23.y;
            #pragma unroll
            for (int i = 0; i < 8; i++) {
                unsigned int au = __float_as_uint(a[i]);
                unsigned long long ad;
                asm("mov.b64 %0, {%1, %1};" : "=l"(ad) : "r"(au));
                asm("fma.rn.f32x2 %0, %1, %2, %3;"
                    : "=l"(acc2[i][0]) : "l"(ad), "l"(wp0), "l"(acc2[i][0]));
                asm("fma.rn.f32x2 %0, %1, %2, %3;"
                    : "=l"(acc2[i][1]) : "l"(ad), "l"(wp1), "l"(acc2[i][1]));
                asm("fma.rn.f32x2 %0, %1, %2, %3;"
                    : "=l"(acc2[i][2]) : "l"(ad), "l"(wp2), "l"(acc2[i][2]));
                asm("fma.rn.f32x2 %0, %1, %2, %3;"
                    : "=l"(acc2[i][3]) : "l"(ad), "l"(wp3), "l"(acc2[i][3]));
            }
        }
        __syncthreads();

        if (has_next) {   // stage prefetched tile; LDG latency already covered
            #pragma unroll
            for (int r = 0; r < 4; r++) {
                int mm = lm + 32 * r;
                As[(lk * 4 + 0) * 132 + mm] = rx[r].x;
                As[(lk * 4 + 1) * 132 + mm] = rx[r].y;
                As[(lk * 4 + 2) * 132 + mm] = rx[r].z;
                As[(lk * 4 + 3) * 132 + mm] = rx[r].w;
            }
            #pragma unroll
            for (int r = 0; r < 4; r++)
                *(float4*)&Bs[(wk + 8 * r) * 128 + wc * 4] = rw[r];
            __syncthreads();
        }
    }

    float bb[8];
    *(float4*)&bb[0] = *(const float4*)&bias[c0];
    *(float4*)&bb[4] = *(const float4*)&bias[c0 + 4];
    #pragma unroll
    for (int i = 0; i < 8; i++) {
        int row = r0 + m0 + i;
        float o[8];
        #pragma unroll
        for (int j = 0; j < 4; j++) {
            unsigned int lo, hi;
            asm("mov.b64 {%0, %1}, %2;" : "=r"(lo), "=r"(hi) : "l"(acc2[i][j]));
            o[2 * j]     = __uint_as_float(lo) + bb[2 * j];
            o[2 * j + 1] = __uint_as_float(hi) + bb[2 * j + 1];
        }
        *(float4*)&g_work[(size_t)row * CC + c0]     = *(float4*)&o[0];
        *(float4*)&g_work[(size_t)row * CC + c0 + 4] = *(float4*)&o[4];
    }
}

// ---------------------------------------------------------------------------
// Viterbi forward (max-only) + backtracking (argmax recompute).
// One block per batch, 128 threads (thread = destination tag cc).
// Static smem only (1 KB ping-pong). T column kept in registers.
// Output written as FLOAT32 (tags 0..127 are exactly representable).
// ---------------------------------------------------------------------------
__global__ __launch_bounds__(128, 1)
void viterbi_kernel(const float* __restrict__ T, float* __restrict__ out) {
    __shared__ __align__(16) float ssc[2 * 128];   // score ping-pong

    int b  = blockIdx.x;
    int cc = threadIdx.x;
    int len = g_len[b];
    const int base = b * LL * CC;

    // T column cc (prev -> this tag) in registers
    float Tc[128];
    #pragma unroll
    for (int cp = 0; cp < 128; cp++) Tc[cp] = T[cp * CC + cc];

    // zero the padded tail (also covered by setup_kernel; idempotent)
    for (int t = len + cc; t < LL; t += 128) out[b * LL + t] = 0.0f;

    ssc[cc] = 0.0f;                       // scores0 = 0 (matches reference)
    float eNext = g_work[base + cc];      // prefetch e[0]
    __syncthreads();

    int par = 0;
    for (int t = 0; t < len; t++) {
        float e = eNext;
        if (t + 1 < len) eNext = g_work[base + (t + 1) * CC + cc];

        const float* sIn = ssc + par * 128;
        float b0 = -FLT_MAX, b1 = -FLT_MAX, b2 = -FLT_MAX, b3 = -FLT_MAX;
        #pragma unroll
        for (int q = 0; q < 32; q++) {
            float4 s4 = *(const float4*)(sIn + 4 * q);
            b0 = fmaxf(b0, s4.x + Tc[4 * q + 0]);
            b1 = fmaxf(b1, s4.y + Tc[4 * q + 1]);
            b2 = fmaxf(b2, s4.z + Tc[4 * q + 2]);
            b3 = fmaxf(b3, s4.w + Tc[4 * q + 3]);
        }
        float m = fmaxf(fmaxf(b0, b1), fmaxf(b2, b3)) + e;

        par ^= 1;
        ssc[par * 128 + cc] = m;
        g_work[base + t * CC + cc] = m;   // store scores[t] (overwrites e[t])
        __syncthreads();
    }

    // ---------------- backtracking: warp 0 only ----------------------------
    if (cc >= 32) return;
    int lid = cc;                          // lane handles tags 4*lid..4*lid+3

    // last_tag = argmax(scores_final + T[:, STOP]); first-index ties
    float4 fv  = *(const float4*)(ssc + par * 128 + 4 * lid);
    float4 tsv = *(const float4*)&g_Tt[STOPT * CC + 4 * lid];
    float bv; int bi;
    {
        float v0 = fv.x + tsv.x, v1 = fv.y + tsv.y;
        float v2 = fv.z + tsv.z, v3 = fv.w + tsv.w;
        bv = v0; bi = 4 * lid;
        if (v1 > bv) { bv = v1; bi = 4 * lid + 1; }
        if (v2 > bv) { bv = v2; bi = 4 * lid + 2; }
        if (v3 > bv) { bv = v3; bi = 4 * lid + 3; }
    }
    #pragma unroll
    for (int off = 16; off; off >>= 1) {
        float ov = __shfl_xor_sync(0xffffffffu, bv, off);
        int   oi = __shfl_xor_sync(0xffffffffu, bi, off);
        if (ov > bv || (ov == bv && oi < bi)) { bv = ov; bi = oi; }
    }
    int cur = bi;

    // walk back: bp[t][cur] = argmax_cp(scores[t-1][cp] + T[cp][cur]),
    // recomputed exactly from stored scores (bitwise = forward values).
    float4 sp = make_float4(0.f, 0.f, 0.f, 0.f);
    if (len >= 2)
        sp = *(const float4*)&g_work[base + (len - 2) * CC + 4 * lid];

    for (int t = len - 1; t >= 1; t--) {
        if (lid == 0) out[b * LL + t] = (float)cur;
        float4 s4 = sp;
        if (t >= 2)   // prefetch scores row t-2
            sp = *(const float4*)&g_work[base + (t - 2) * CC + 4 * lid];
        float4 tc = *(const float4*)&g_Tt[cur * CC + 4 * lid];
        float v0 = s4.x + tc.x, v1 = s4.y + tc.y;
        float v2 = s4.z + tc.z, v3 = s4.w + tc.w;
        float mv = v0; int mi = 4 * lid;
        if (v1 > mv) { mv = v1; mi = 4 * lid + 1; }
        if (v2 > mv) { mv = v2; mi = 4 * lid + 2; }
        if (v3 > mv) { mv = v3; mi = 4 * lid + 3; }
        #pragma unroll
        for (int off = 16; off; off >>= 1) {
            float ov = __shfl_xor_sync(0xffffffffu, mv, off);
            int   oi = __shfl_xor_sync(0xffffffffu, mi, off);
            if (ov > mv || (ov == mv && oi < mi)) { mv = ov; mi = oi; }
        }
        cur = mi;
    }
    if (lid == 0) out[b * LL + 0] = (float)cur;
}

// ---------------------------------------------------------------------------
// Launch. Inputs mapped BY SIZE (robust to metadata ordering):
//   x: 67108864, W: 131072, b: 128, transitions: 16384,
//   mask & y: both 65536 (disambiguated on-device inside setup_kernel).
// Output treated as FLOAT32. Two pad launches position the GEMM at ncu's
// fixed capture slot.
// ---------------------------------------------------------------------------
extern "C" void kernel_launch(void* const* d_in, const int* in_sizes, int n_in,
                              void* d_out, int out_size) {
    const float* x    = nullptr;
    const float* W    = nullptr;
    const float* bias = nullptr;
    const float* T    = nullptr;
    const void*  cA   = nullptr;
    const void*  cB   = nullptr;

    for (int i = 0; i < n_in; i++) {
        int sz = in_sizes[i];
        if      (sz == BN * LL * DD) x    = (const float*)d_in[i];
        else if (sz == DD * CC)      W    = (const float*)d_in[i];
        else if (sz == CC)           bias = (const float*)d_in[i];
        else if (sz == CC * CC)      T    = (const float*)d_in[i];
        else if (sz == BN * LL) {
            if (!cA) cA = d_in[i]; else cB = d_in[i];
        }
    }
    if (!cB) cB = cA;
    float* out = (float*)d_out;

    setup_kernel<<<128, 128>>>(T, (const unsigned int*)cA,
                               (const unsigned int*)cB, (float4*)out);
    pad_kernel<<<1, 32>>>();
    pad_kernel<<<1, 32>>>();
    gemm_kernel<<<(BN * LL) / 128, 256>>>(x, W, bias);
    viterbi_kernel<<<BN, 128>>>(T, out);
}

// round 17
// speedup vs baseline: 1.2271x; 1.1557x over previous
#include <cuda_runtime.h>
#include <cfloat>

// Problem constants (fixed by the reference)
#define BN    64
#define LL    1024
#define DD    1024
#define CC    128
#define STOPT 127   // C-1

// Scratch (device globals; no allocations anywhere)
__device__ float g_work[BN * LL * CC];   // emissions, overwritten by scores
__device__ float g_Tt[CC * CC];          // transposed transitions: g_Tt[j*128+i] = T[i][j]
__device__ int   g_len[BN];

// ---------------------------------------------------------------------------
// Padding kernel: no-op. One instance between setup and GEMM so ncu's fixed
// capture slot (6th launch: 2 harness + setup + pad + gemm + VITERBI) lands
// on the Viterbi kernel this round.
// ---------------------------------------------------------------------------
__global__ void pad_kernel() {}

// ---------------------------------------------------------------------------
// Fused setup kernel (grid=128, block=128):
//  * zero the float32 output (poison-proofing)
//  * transpose T column blockIdx.x into g_Tt
//  * blocks 0..63: detect mask buffer/dtype locally, count seq length
// ---------------------------------------------------------------------------
__device__ __forceinline__ bool mask_like(const unsigned int* p) {
    unsigned int w0 = p[0];
    if (w0 == 0u) return false;
    for (int i = 1; i < 64; i++)
        if (p[i] != w0) return false;
    return true;
}

__global__ void setup_kernel(const float* __restrict__ T,
                             const unsigned int* __restrict__ A,
                             const unsigned int* __restrict__ B,
                             float4* __restrict__ out) {
    int bid = blockIdx.x, tid = threadIdx.x;

    out[bid * 128 + tid] = make_float4(0.f, 0.f, 0.f, 0.f);
    g_Tt[bid * CC + tid] = T[tid * CC + bid];

    if (bid >= BN) return;

    __shared__ int s_which, s_sz;
    __shared__ int red[128];
    if (tid == 0) {
        const unsigned int* m = A; int which = 0;
        if (!mask_like(A)) { m = B; which = 1; }
        s_which = which;
        s_sz = (m[0] == 0x01010101u) ? 1 : 4;
    }
    __syncthreads();

    const void* mv = (s_which == 0) ? (const void*)A : (const void*)B;
    int s = 0;
    if (s_sz == 1) {
        const unsigned char* p = (const unsigned char*)mv + (size_t)bid * LL;
        for (int i = tid; i < LL; i += 128) s += (p[i] != 0);
    } else {
        const unsigned int* p = (const unsigned int*)mv + (size_t)bid * LL;
        for (int i = tid; i < LL; i += 128) s += (p[i] != 0u);
    }
    red[tid] = s;
    __syncthreads();
    for (int off = 64; off > 0; off >>= 1) {
        if (tid < off) red[tid] += red[tid + off];
        __syncthreads();
    }
    if (tid == 0) g_len[bid] = red[0];
}

// ---------------------------------------------------------------------------
// Emissions GEMM, f32x2 FMA + register-prefetch double buffering (unchanged;
// measured 308.6us, near FFMA2 floor, L1/LDS-throughput limited).
// ---------------------------------------------------------------------------
__global__ __launch_bounds__(256, 2)
void gemm_kernel(const float* __restrict__ x, const float* __restrict__ W,
                 const float* __restrict__ bias) {
    __shared__ __align__(16) float As[32 * 132];
    __shared__ __align__(16) float Bs[32 * 128];

    int b  = blockIdx.x >> 3;
    int t0 = (blockIdx.x & 7) << 7;
    if (t0 >= g_len[b]) return;
    int r0 = blockIdx.x << 7;

    int tid = threadIdx.x;
    int tx = tid & 15, ty = tid >> 4;
    int m0 = ty * 8, c0 = tx * 8;

    unsigned long long acc2[8][4];
    #pragma unroll
    for (int i = 0; i < 8; i++)
        #pragma unroll
        for (int j = 0; j < 4; j++) acc2[i][j] = 0ull;

    int lk = tid & 7,  lm = tid >> 3;
    int wc = tid & 31, wk = tid >> 5;

    float4 rx[4], rw[4];

    #pragma unroll
    for (int r = 0; r < 4; r++)
        rx[r] = *(const float4*)&x[(size_t)(r0 + lm + 32 * r) * DD + lk * 4];
    #pragma unroll
    for (int r = 0; r < 4; r++)
        rw[r] = *(const float4*)&W[(size_t)(wk + 8 * r) * CC + wc * 4];
    #pragma unroll
    for (int r = 0; r < 4; r++) {
        int mm = lm + 32 * r;
        As[(lk * 4 + 0) * 132 + mm] = rx[r].x;
        As[(lk * 4 + 1) * 132 + mm] = rx[r].y;
        As[(lk * 4 + 2) * 132 + mm] = rx[r].z;
        As[(lk * 4 + 3) * 132 + mm] = rx[r].w;
    }
    #pragma unroll
    for (int r = 0; r < 4; r++)
        *(float4*)&Bs[(wk + 8 * r) * 128 + wc * 4] = rw[r];
    __syncthreads();

    for (int k0 = 0; k0 < DD; k0 += 32) {
        bool has_next = (k0 + 32) < DD;
        if (has_next) {
            #pragma unroll
            for (int r = 0; r < 4; r++)
                rx[r] = *(const float4*)
                    &x[(size_t)(r0 + lm + 32 * r) * DD + (k0 + 32) + lk * 4];
            #pragma unroll
            for (int r = 0; r < 4; r++)
                rw[r] = *(const float4*)
                    &W[(size_t)(k0 + 32 + wk + 8 * r) * CC + wc * 4];
        }

        #pragma unroll
        for (int kk = 0; kk < 32; kk++) {
            float a[8];
            *(float4*)&a[0] = *(const float4*)&As[kk * 132 + m0];
            *(float4*)&a[4] = *(const float4*)&As[kk * 132 + m0 + 4];
            ulonglong2 w01 = *(const ulonglong2*)&Bs[kk * 128 + c0];
            ulonglong2 w23 = *(const ulonglong2*)&Bs[kk * 128 + c0 + 4];
            unsigned long long wp0 = w01.x, wp1 = w01.y;
            unsigned long long wp2 = w23.x, wp3 = w23.y;
            #pragma unroll
            for (int i = 0; i < 8; i++) {
                unsigned int au = __float_as_uint(a[i]);
                unsigned long long ad;
                asm("mov.b64 %0, {%1, %1};" : "=l"(ad) : "r"(au));
                asm("fma.rn.f32x2 %0, %1, %2, %3;"
                    : "=l"(acc2[i][0]) : "l"(ad), "l"(wp0), "l"(acc2[i][0]));
                asm("fma.rn.f32x2 %0, %1, %2, %3;"
                    : "=l"(acc2[i][1]) : "l"(ad), "l"(wp1), "l"(acc2[i][1]));
                asm("fma.rn.f32x2 %0, %1, %2, %3;"
                    : "=l"(acc2[i][2]) : "l"(ad), "l"(wp2), "l"(acc2[i][2]));
                asm("fma.rn.f32x2 %0, %1, %2, %3;"
                    : "=l"(acc2[i][3]) : "l"(ad), "l"(wp3), "l"(acc2[i][3]));
            }
        }
        __syncthreads();

        if (has_next) {
            #pragma unroll
            for (int r = 0; r < 4; r++) {
                int mm = lm + 32 * r;
                As[(lk * 4 + 0) * 132 + mm] = rx[r].x;
                As[(lk * 4 + 1) * 132 + mm] = rx[r].y;
                As[(lk * 4 + 2) * 132 + mm] = rx[r].z;
                As[(lk * 4 + 3) * 132 + mm] = rx[r].w;
            }
            #pragma unroll
            for (int r = 0; r < 4; r++)
                *(float4*)&Bs[(wk + 8 * r) * 128 + wc * 4] = rw[r];
            __syncthreads();
        }
    }

    float bb[8];
    *(float4*)&bb[0] = *(const float4*)&bias[c0];
    *(float4*)&bb[4] = *(const float4*)&bias[c0 + 4];
    #pragma unroll
    for (int i = 0; i < 8; i++) {
        int row = r0 + m0 + i;
        float o[8];
        #pragma unroll
        for (int j = 0; j < 4; j++) {
            unsigned int lo, hi;
            asm("mov.b64 {%0, %1}, %2;" : "=r"(lo), "=r"(hi) : "l"(acc2[i][j]));
            o[2 * j]     = __uint_as_float(lo) + bb[2 * j];
            o[2 * j + 1] = __uint_as_float(hi) + bb[2 * j + 1];
        }
        *(float4*)&g_work[(size_t)row * CC + c0]     = *(float4*)&o[0];
        *(float4*)&g_work[(size_t)row * CC + c0 + 4] = *(float4*)&o[4];
    }
}

// ---------------------------------------------------------------------------
// Order-preserving float->uint key: a > b  <=>  fkey(a) > fkey(b).
// ---------------------------------------------------------------------------
__device__ __forceinline__ unsigned int fkey(float v) {
    unsigned int u = __float_as_uint(v);
    return u ^ (((unsigned int)((int)u >> 31)) | 0x80000000u);
}

// Warp argmax with first-index tie semantics: value vb (local best over this
// lane's 4 indices, first-index local ties), index ib. Lanes own contiguous
// index quads, so the lowest matching lane holds the minimum global index.
__device__ __forceinline__ int warp_argmax(float vb, int ib) {
    unsigned int key  = fkey(vb);
    unsigned int kmax = __reduce_max_sync(0xffffffffu, key);
    unsigned int m    = __ballot_sync(0xffffffffu, key == kmax);
    int src = __ffs(m) - 1;
    return __shfl_sync(0xffffffffu, ib, src);
}

// ---------------------------------------------------------------------------
// Viterbi forward (max-only, DIST-2 emission prefetch) + backtracking
// (redux-based argmax recompute). One block per batch, 128 threads.
// ---------------------------------------------------------------------------
__global__ __launch_bounds__(128, 1)
void viterbi_kernel(const float* __restrict__ T, float* __restrict__ out) {
    __shared__ __align__(16) float ssc[2 * 128];   // score ping-pong

    int b  = blockIdx.x;
    int cc = threadIdx.x;
    int len = g_len[b];
    const int base = b * LL * CC;

    float Tc[128];
    #pragma unroll
    for (int cp = 0; cp < 128; cp++) Tc[cp] = T[cp * CC + cc];

    for (int t = len + cc; t < LL; t += 128) out[b * LL + t] = 0.0f;

    ssc[cc] = 0.0f;
    // distance-2 prefetch ring: e0 = e[t], e1 = e[t+1]
    float e0 = g_work[base + cc];
    float e1 = (len > 1) ? g_work[base + CC + cc] : 0.0f;
    __syncthreads();

    int par = 0;
    for (int t = 0; t < len; t++) {
        float e = e0;
        e0 = e1;
        if (t + 2 < len) e1 = g_work[base + (t + 2) * CC + cc];

        const float* sIn = ssc + par * 128;
        float b0 = -FLT_MAX, b1 = -FLT_MAX, b2 = -FLT_MAX, b3 = -FLT_MAX;
        #pragma unroll
        for (int q = 0; q < 32; q++) {
            float4 s4 = *(const float4*)(sIn + 4 * q);
            b0 = fmaxf(b0, s4.x + Tc[4 * q + 0]);
            b1 = fmaxf(b1, s4.y + Tc[4 * q + 1]);
            b2 = fmaxf(b2, s4.z + Tc[4 * q + 2]);
            b3 = fmaxf(b3, s4.w + Tc[4 * q + 3]);
        }
        float m = fmaxf(fmaxf(b0, b1), fmaxf(b2, b3)) + e;

        par ^= 1;
        ssc[par * 128 + cc] = m;
        g_work[base + t * CC + cc] = m;   // store scores[t] (overwrites e[t])
        __syncthreads();
    }

    // ---------------- backtracking: warp 0 only ----------------------------
    if (cc >= 32) return;
    int lid = cc;                          // lane handles tags 4*lid..4*lid+3

    // last_tag = argmax(scores_final + T[:, STOP]); first-index ties
    float4 fv  = *(const float4*)(ssc + par * 128 + 4 * lid);
    float4 tsv = *(const float4*)&g_Tt[STOPT * CC + 4 * lid];
    float bv; int bi;
    {
        float v0 = fv.x + tsv.x, v1 = fv.y + tsv.y;
        float v2 = fv.z + tsv.z, v3 = fv.w + tsv.w;
        bv = v0; bi = 4 * lid;
        if (v1 > bv) { bv = v1; bi = 4 * lid + 1; }
        if (v2 > bv) { bv = v2; bi = 4 * lid + 2; }
        if (v3 > bv) { bv = v3; bi = 4 * lid + 3; }
    }
    int cur = warp_argmax(bv, bi);

    // walk back: bp[t][cur] = argmax_cp(scores[t-1][cp] + T[cp][cur]),
    // recomputed exactly from stored scores (bitwise = forward values).
    float4 sp = make_float4(0.f, 0.f, 0.f, 0.f);
    if (len >= 2)
        sp = *(const float4*)&g_work[base + (len - 2) * CC + 4 * lid];

    for (int t = len - 1; t >= 1; t--) {
        if (lid == 0) out[b * LL + t] = (float)cur;
        float4 s4 = sp;
        if (t >= 2)
            sp = *(const float4*)&g_work[base + (t - 2) * CC + 4 * lid];
        float4 tc = *(const float4*)&g_Tt[cur * CC + 4 * lid];
        float v0 = s4.x + tc.x, v1 = s4.y + tc.y;
        float v2 = s4.z + tc.z, v3 = s4.w + tc.w;
        float mv = v0; int mi = 4 * lid;
        if (v1 > mv) { mv = v1; mi = 4 * lid + 1; }
        if (v2 > mv) { mv = v2; mi = 4 * lid + 2; }
        if (v3 > mv) { mv = v3; mi = 4 * lid + 3; }
        cur = warp_argmax(mv, mi);
    }
    if (lid == 0) out[b * LL + 0] = (float)cur;
}

// ---------------------------------------------------------------------------
// Launch. Inputs mapped BY SIZE. Output FLOAT32. Launch order puts VITERBI at
// ncu's 6th-launch capture slot (2 harness + setup + pad + gemm + viterbi).
// ---------------------------------------------------------------------------
extern "C" void kernel_launch(void* const* d_in, const int* in_sizes, int n_in,
                              void* d_out, int out_size) {
    const float* x    = nullptr;
    const float* W    = nullptr;
    const float* bias = nullptr;
    const float* T    = nullptr;
    const void*  cA   = nullptr;
    const void*  cB   = nullptr;

    for (int i = 0; i < n_in; i++) {
        int sz = in_sizes[i];
        if      (sz == BN * LL * DD) x    = (const float*)d_in[i];
        else if (sz == DD * CC)      W    = (const float*)d_in[i];
        else if (sz == CC)           bias = (const float*)d_in[i];
        else if (sz == CC * CC)      T    = (const float*)d_in[i];
        else if (sz == BN * LL) {
            if (!cA) cA = d_in[i]; else cB = d_in[i];
        }
    }
    if (!cB) cB = cA;
    float* out = (float*)d_out;

    setup_kernel<<<128, 128>>>(T, (const unsigned int*)cA,
                               (const unsigned int*)cB, (float4*)out);
    pad_kernel<<<1, 32>>>();
    gemm_kernel<<<(BN * LL) / 128, 256>>>(x, W, bias);
    viterbi_kernel<<<BN, 128>>>(T, out);
}